// round 15
// baseline (speedup 1.0000x reference)
#include <cuda_runtime.h>
#include <cuda_fp16.h>
#include <mma.h>
#include <cstdint>

using namespace nvcuda;

// Problem dims (fixed by setup_inputs)
constexpr int U = 128, I = 256, J = 512, C = 128, E = 128;

// ---------------- scratch (device globals; zero-init) ------------------------
__device__ float  g_skb[U * J];            // inter . w2 + b
__device__ float  g_upart_unused;          // (upart now block-local)
__device__ __half g_Zh[U * J * C];         // Z = interacted @ W2, fp16
__device__ int    g_flag[2 * U];           // per (u, half) Z-ready flags

// ---------------- low-level helpers ------------------------------------------
__device__ __forceinline__ void cp_async16(void* smem, const void* gmem)
{
    unsigned s = (unsigned)__cvta_generic_to_shared(smem);
    asm volatile("cp.async.cg.shared.global [%0], [%1], 16;" :: "r"(s), "l"(gmem));
}
__device__ __forceinline__ void cp_commit()
{
    asm volatile("cp.async.commit_group;" ::: "memory");
}
template<int N>
__device__ __forceinline__ void cp_wait()
{
    asm volatile("cp.async.wait_group %0;" :: "n"(N) : "memory");
}
__device__ __forceinline__ int ld_acquire(const int* p)
{
    int v;
    asm volatile("ld.acquire.gpu.global.s32 %0, [%1];" : "=r"(v) : "l"(p));
    return v;
}

// BM=128 warp tile (acc[4][2]), depth 128, 8 warps (2x4)
template<int LDA, int LDB>
__device__ __forceinline__ void mma_tile128_d128(
    const __half* A, const __half* B, int wm, int wn,
    wmma::fragment<wmma::accumulator, 16, 16, 16, float> (&acc)[4][2])
{
    #pragma unroll
    for (int kk = 0; kk < 128; kk += 16) {
        wmma::fragment<wmma::matrix_a, 16, 16, 16, __half, wmma::row_major> a[4];
        wmma::fragment<wmma::matrix_b, 16, 16, 16, __half, wmma::row_major> b[2];
        #pragma unroll
        for (int fi = 0; fi < 4; fi++)
            wmma::load_matrix_sync(a[fi], A + (wm * 64 + fi * 16) * LDA + kk, LDA);
        #pragma unroll
        for (int fj = 0; fj < 2; fj++)
            wmma::load_matrix_sync(b[fj], B + kk * LDB + wn * 32 + fj * 16, LDB);
        #pragma unroll
        for (int fi = 0; fi < 4; fi++)
            #pragma unroll
            for (int fj = 0; fj < 2; fj++)
                wmma::mma_sync(acc[fi][fj], a[fi], b[fj], acc[fi][fj]);
    }
}

// ---------------- smem layout -------------------------------------------------
// Region W (133,120 B): wsm 128x520 half  | phase A: AsZ 256x136 half, CsZ 256x128 f32
// Region B (69,632 B) : Bs [2][128*136]   | phase A: W2h 128x136 half
// Small: st(128f) inv(128f) skb(512f) m(512f|psum) up(128f) sniff(16B)
constexpr int LDW   = 520;
constexpr int WOFF  = 0;
constexpr int WSZ   = 128 * LDW * 2;               // 133,120
constexpr int BOFF  = WSZ;                         // 133,120
constexpr int BS_STAGE = 128 * 136;                // halves
constexpr int BSZ   = 2 * BS_STAGE * 2;            // 69,632
constexpr int SOFF  = BOFF + BSZ;                  // 202,752
constexpr int SMEM_TOTAL = SOFF + (128 + 128 + 512 + 512 + 128) * 4 + 16; // 208,416

__global__ __launch_bounds__(512, 1) void mega_kernel(
    const float* __restrict__ target, const float* __restrict__ inter,
    const float* __restrict__ user,   const void*  __restrict__ mask,
    const float* __restrict__ wdense, const float* __restrict__ bdense,
    const float* __restrict__ Wmlp,   const float* __restrict__ bmlp,
    float* __restrict__ out_ctx, float* __restrict__ out_attn)
{
    extern __shared__ __align__(16) char dsm[];
    __half* wsm    = (__half*)(dsm + WOFF);     // phase B softmax tile
    __half* AsZ    = (__half*)(dsm + WOFF);     // phase A: inter fp16 (256x136)
    float*  CsZ    = (float*)(dsm + WOFF);      // phase A: Z staging (256x128)
    float*  Cs     = (float*)(dsm + WOFF);      // phase B epilogue staging
    __half* Bs     = (__half*)(dsm + BOFF);     // phase B: Zh tiles
    __half* W2h    = (__half*)(dsm + BOFF);     // phase A: W2 fp16 (128x136)
    float*  st_sm  = (float*)(dsm + SOFF);
    float*  inv_sm = st_sm + 128;
    float*  skb_sm = inv_sm + 128;
    float*  m_sm   = skb_sm + 512;              // phase A: upart psum
    float*  up_sm  = m_sm + 512;
    int*    s_f    = (int*)(up_sm + 128);

    const int h = blockIdx.x, u = blockIdx.y;
    const int j0 = h * 256;                     // own j-half
    const int m0 = h * 128;                     // own i-rows
    const int tid = threadIdx.x, wid = tid >> 5, lane = tid & 31;
    const float L2E = 1.4426950408889634f;

    // ---- sniff sample read (byte-vs-word); resolved after later syncs ----
    if (tid == 0) s_f[0] = 0;
    unsigned sw = ((const unsigned*)mask)[u * 128 + (tid & 127)];
    int bad = (sw != 0u && sw != 1u && sw != 0x3F800000u);

    const float4 wv1 = __ldg((const float4*)wdense + lane);         // w1
    const float4 wv2 = __ldg((const float4*)(wdense + C) + lane);   // w2
    const float bias = __ldg(bdense);

    // =================== PHASE A: produce Z half, st, upart ===================
    // (A1) inter rows j0..j0+255 -> AsZ fp16 + skb (warp-per-row, 16 rows/warp)
    #pragma unroll
    for (int half = 0; half < 2; half++) {
        float4 v[8];
        #pragma unroll
        for (int r = 0; r < 8; r++)
            v[r] = *(const float4*)(inter +
                ((size_t)(u * J + j0 + half * 128 + wid + 16 * r)) * C + lane * 4);
        #pragma unroll
        for (int r = 0; r < 8; r++) {
            int row = half * 128 + wid + 16 * r;      // 0..255
            __half2 h01 = __floats2half2_rn(v[r].x, v[r].y);
            __half2 h23 = __floats2half2_rn(v[r].z, v[r].w);
            uint2 pk; pk.x = *(unsigned*)&h01; pk.y = *(unsigned*)&h23;
            *(uint2*)(AsZ + row * 136 + lane * 4) = pk;
            float d = v[r].x * wv2.x + v[r].y * wv2.y + v[r].z * wv2.z + v[r].w * wv2.w;
            #pragma unroll
            for (int off = 16; off; off >>= 1) d += __shfl_xor_sync(0xffffffffu, d, off);
            if (lane == 0) {
                float s = d + bias;
                skb_sm[j0 + row] = s;
                g_skb[u * J + j0 + row] = s;
            }
        }
    }
    // (A2) st for own 128 i-rows (warp-per-row, 8 rows/warp) -> st_sm only
    {
        float4 tv[8];
        #pragma unroll
        for (int r = 0; r < 8; r++)
            tv[r] = *(const float4*)(target +
                ((size_t)(u * I + m0 + wid + 16 * r)) * C + lane * 4);
        #pragma unroll
        for (int r = 0; r < 8; r++) {
            float d = tv[r].x * wv1.x + tv[r].y * wv1.y + tv[r].z * wv1.z + tv[r].w * wv1.w;
            #pragma unroll
            for (int off = 16; off; off >>= 1) d += __shfl_xor_sync(0xffffffffu, d, off);
            if (lane == 0) st_sm[wid + 16 * r] = d;
        }
    }
    // sniff reduce
    bad = __reduce_or_sync(0xffffffffu, bad);
    if (lane == 0 && bad) atomicOr(&s_f[0], 1);

    // (A3) upart (redundant per block): up_sm = user[u] @ Wmlp[:E] + bmlp
    if (tid < 128) up_sm[tid] = user[u * E + tid];
    __syncthreads();
    {
        int c = tid & 127, q = tid >> 7;              // q in 0..3, 32 e's each
        float a0 = 0.f;
        #pragma unroll 8
        for (int e = 0; e < 32; e++)
            a0 += up_sm[q * 32 + e] * __ldg(Wmlp + (q * 32 + e) * C + c);
        m_sm[tid] = a0;                               // psum staging
    }
    // (A4) W2 -> W2h fp16 (over Bs region)
    #pragma unroll
    for (int r = 0; r < 4; r++) {
        int idx = tid + 512 * r;                      // 2048 chunks
        int br = idx >> 4, bc = (idx & 15) * 8;
        float4 t0 = __ldg((const float4*)(Wmlp + (size_t)(E + br) * C + bc));
        float4 t1 = __ldg((const float4*)(Wmlp + (size_t)(E + br) * C + bc + 4));
        __half2 a01 = __floats2half2_rn(t0.x, t0.y);
        __half2 a23 = __floats2half2_rn(t0.z, t0.w);
        __half2 b01 = __floats2half2_rn(t1.x, t1.y);
        __half2 b23 = __floats2half2_rn(t1.z, t1.w);
        uint4 pk;
        pk.x = *(unsigned*)&a01; pk.y = *(unsigned*)&a23;
        pk.z = *(unsigned*)&b01; pk.w = *(unsigned*)&b23;
        *(uint4*)(W2h + br * 136 + bc) = pk;
    }
    __syncthreads();
    if (tid < 128)
        up_sm[tid] = m_sm[tid] + m_sm[tid + 128] + m_sm[tid + 256] + m_sm[tid + 384]
                   + __ldg(bmlp + tid);

    // (A5) Z MMA: AsZ (256x128) @ W2h (128x128) -> acc, 16 warps (4x4)
    {
        const int wmz = wid >> 2, wnz = wid & 3;
        wmma::fragment<wmma::accumulator, 16, 16, 16, float> accz[4][2];
        #pragma unroll
        for (int fi = 0; fi < 4; fi++)
            for (int fj = 0; fj < 2; fj++) wmma::fill_fragment(accz[fi][fj], 0.f);
        mma_tile128_d128<136, 136>(AsZ + (wmz * 64) * 136 - (wmz * 64) * 136
                                   + (wmz * 64) * 136, W2h, 0, 0, accz); // placeholder avoided below
        // NOTE: the helper assumes wm*64 internally; call with explicit mapping:
        // (re-done manually to map 4x4 warp grid)
        #pragma unroll
        for (int fi = 0; fi < 4; fi++)
            for (int fj = 0; fj < 2; fj++) wmma::fill_fragment(accz[fi][fj], 0.f);
        #pragma unroll
        for (int kk = 0; kk < 128; kk += 16) {
            wmma::fragment<wmma::matrix_a, 16, 16, 16, __half, wmma::row_major> a[4];
            wmma::fragment<wmma::matrix_b, 16, 16, 16, __half, wmma::row_major> b[2];
            #pragma unroll
            for (int fi = 0; fi < 4; fi++)
                wmma::load_matrix_sync(a[fi], AsZ + (wmz * 64 + fi * 16) * 136 + kk, 136);
            #pragma unroll
            for (int fj = 0; fj < 2; fj++)
                wmma::load_matrix_sync(b[fj], W2h + kk * 136 + wnz * 32 + fj * 16, 136);
            #pragma unroll
            for (int fi = 0; fi < 4; fi++)
                #pragma unroll
                for (int fj = 0; fj < 2; fj++)
                    wmma::mma_sync(accz[fi][fj], a[fi], b[fj], accz[fi][fj]);
        }
        __syncthreads();   // all warps done reading AsZ
        #pragma unroll
        for (int fi = 0; fi < 4; fi++)
            for (int fj = 0; fj < 2; fj++)
                wmma::store_matrix_sync(
                    CsZ + (wmz * 64 + fi * 16) * 128 + wnz * 32 + fj * 16,
                    accz[fi][fj], 128, wmma::mem_row_major);
        __syncthreads();
    }
    // (A6) CsZ -> g_Zh fp16 (own half)
    #pragma unroll
    for (int it = 0; it < 16; it++) {
        int idx = tid + 512 * it;                     // 8192 float4s
        int row = idx >> 5, c4 = (idx & 31) * 4;
        float4 t = *(const float4*)(CsZ + row * 128 + c4);
        __half2 h01 = __floats2half2_rn(t.x, t.y);
        __half2 h23 = __floats2half2_rn(t.z, t.w);
        uint2 pk; pk.x = *(unsigned*)&h01; pk.y = *(unsigned*)&h23;
        *(uint2*)(g_Zh + ((size_t)(u * J + j0 + row)) * C + c4) = pk;
    }
    __syncthreads();
    __threadfence();
    if (tid == 0) atomicExch(&g_flag[u * 2 + h], 1);

    // =================== PHASE B: softmax + pooling + MLP =====================
    const int bytemode = s_f[0];

    // mask -> m_sm (psum no longer needed)
    if (bytemode) m_sm[tid] = ((const unsigned char*)mask)[u * J + tid] ? 1.f : 0.f;
    else          m_sm[tid] = ((const unsigned*)mask)[u * J + tid] ? 1.f : 0.f;

    // prefetch own first Bs tile (tile 2h; own data, L2-hot)
    if (tid < 256) {
        #pragma unroll
        for (int r = 0; r < 8; r++) {
            int idx = tid + 256 * r;                  // 2048 chunks
            int br = idx >> 4, bc = (idx & 15) * 8;
            cp_async16(Bs + br * 136 + bc,
                       g_Zh + ((size_t)(u * J + 2 * h * 128 + br)) * C + bc);
        }
        cp_commit();
    }
    __syncthreads();

    // own-half w (4 thr/row, 32 pairs)
    const int row = tid >> 2, sub = tid & 3;
    const float stv = st_sm[row];
    float sum = 0.f;
    #pragma unroll
    for (int k = 0; k < 32; k++) {
        int c = j0 + sub * 2 + 8 * k;
        float x0 = stv + skb_sm[c], x1 = stv + skb_sm[c + 1];
        float t0, t1, e0, e1;
        asm("tanh.approx.f32 %0,%1;" : "=f"(t0) : "f"(x0));
        asm("tanh.approx.f32 %0,%1;" : "=f"(t1) : "f"(x1));
        asm("ex2.approx.f32 %0,%1;"  : "=f"(e0) : "f"(t0 * L2E));
        asm("ex2.approx.f32 %0,%1;"  : "=f"(e1) : "f"(t1 * L2E));
        e0 *= m_sm[c]; e1 *= m_sm[c + 1];
        *(__half2*)(wsm + row * LDW + c) = __floats2half2_rn(e0, e1);
        sum += e0 + e1;
    }

    // wait for partner Z + skb
    if (tid == 0) {
        const int* pf = &g_flag[u * 2 + (1 - h)];
        while (ld_acquire(pf) == 0) __nanosleep(32);
    }
    __syncthreads();

    // partner skb -> smem; partner-half w
    const int pj0 = 256 - j0;
    if (tid < 256) skb_sm[pj0 + tid] = g_skb[u * J + pj0 + tid];
    __syncthreads();
    #pragma unroll
    for (int k = 0; k < 32; k++) {
        int c = pj0 + sub * 2 + 8 * k;
        float x0 = stv + skb_sm[c], x1 = stv + skb_sm[c + 1];
        float t0, t1, e0, e1;
        asm("tanh.approx.f32 %0,%1;" : "=f"(t0) : "f"(x0));
        asm("tanh.approx.f32 %0,%1;" : "=f"(t1) : "f"(x1));
        asm("ex2.approx.f32 %0,%1;"  : "=f"(e0) : "f"(t0 * L2E));
        asm("ex2.approx.f32 %0,%1;"  : "=f"(e1) : "f"(t1 * L2E));
        e0 *= m_sm[c]; e1 *= m_sm[c + 1];
        *(__half2*)(wsm + row * LDW + c) = __floats2half2_rn(e0, e1);
        sum += e0 + e1;
    }
    sum += __shfl_xor_sync(0xffffffffu, sum, 1);
    sum += __shfl_xor_sync(0xffffffffu, sum, 2);
    if (sub == 0) inv_sm[row] = __fdividef(1.f, sum);
    __syncthreads();

    // MMA (warps 0-7) || attn stores (warps 8-15)
    wmma::fragment<wmma::accumulator, 16, 16, 16, float> acc[4][2];
    const int korder[4] = {2 * h, 2 * h + 1, 2 - 2 * h, 3 - 2 * h};

    if (tid < 256) {
        const int wm = wid >> 2, wn = wid & 3;
        #pragma unroll
        for (int fi = 0; fi < 4; fi++)
            for (int fj = 0; fj < 2; fj++) wmma::fill_fragment(acc[fi][fj], 0.f);

        for (int q = 0; q < 4; q++) {
            if (q < 3) {
                int nt = korder[q + 1];
                __half* dst = Bs + ((q + 1) & 1) * BS_STAGE;
                #pragma unroll
                for (int r = 0; r < 8; r++) {
                    int idx = tid + 256 * r;
                    int br = idx >> 4, bc = (idx & 15) * 8;
                    cp_async16(dst + br * 136 + bc,
                               g_Zh + ((size_t)(u * J + nt * 128 + br)) * C + bc);
                }
                cp_commit();
                cp_wait<1>();
            } else {
                cp_wait<0>();
            }
            asm volatile("bar.sync 1, 256;" ::: "memory");
            mma_tile128_d128<LDW, 136>(wsm + korder[q] * 128,
                                       Bs + (q & 1) * BS_STAGE, wm, wn, acc);
            asm volatile("bar.sync 1, 256;" ::: "memory");
        }
    } else {
        int t = tid - 256;
        float* ab = out_attn + ((size_t)(u * I + m0)) * J;
        #pragma unroll
        for (int it = 0; it < 64; it++) {
            int idx = t + 256 * it;                   // 16384 float4s
            int r2 = idx >> 7, c4 = (idx & 127) * 4;
            uint2 pk = *(uint2*)(wsm + r2 * LDW + c4);
            __half2 h01 = *(__half2*)&pk.x, h23 = *(__half2*)&pk.y;
            float iv = inv_sm[r2];
            float2 f01 = __half22float2(h01), f23 = __half22float2(h23);
            *(float4*)(ab + r2 * J + c4) =
                make_float4(f01.x * iv, f01.y * iv, f23.x * iv, f23.y * iv);
        }
    }
    __syncthreads();   // store warps done with wsm; Cs may alias it

    if (tid < 256) {
        const int wm = wid >> 2, wn = wid & 3;
        #pragma unroll
        for (int fi = 0; fi < 4; fi++)
            for (int fj = 0; fj < 2; fj++)
                wmma::store_matrix_sync(
                    Cs + (wm * 64 + fi * 16) * 128 + wn * 32 + fj * 16,
                    acc[fi][fj], 128, wmma::mem_row_major);
    }
    __syncthreads();

    {
        float* ob = out_ctx + ((size_t)(u * I + m0)) * C;
        #pragma unroll
        for (int it = 0; it < 8; it++) {
            int idx = tid + 512 * it;                 // 4096 float4s
            int r2 = idx >> 5, c4 = (idx & 31) * 4;
            float4 v = *(const float4*)(Cs + r2 * 128 + c4);
            float iv = inv_sm[r2];
            v.x = fmaxf(fmaf(v.x, iv, up_sm[c4 + 0]), 0.f);
            v.y = fmaxf(fmaf(v.y, iv, up_sm[c4 + 1]), 0.f);
            v.z = fmaxf(fmaf(v.z, iv, up_sm[c4 + 2]), 0.f);
            v.w = fmaxf(fmaf(v.w, iv, up_sm[c4 + 3]), 0.f);
            *(float4*)(ob + r2 * C + c4) = v;
        }
    }

    // self-reset: each flag has exactly one consumer (the partner block)
    if (tid == 0) atomicExch(&g_flag[u * 2 + (1 - h)], 0);
}

// ---------------- launcher ---------------------------------------------------
extern "C" void kernel_launch(void* const* d_in, const int* in_sizes, int n_in,
                              void* d_out, int out_size)
{
    const float* target = (const float*)d_in[0];  // (U,I,C)
    const float* inter  = (const float*)d_in[1];  // (U,J,C)
    const float* user   = (const float*)d_in[2];  // (U,E)
    const void*  mask   = d_in[3];                // (U,J) dtype sniffed
    const float* wdense = (const float*)d_in[4];  // (2C,)
    const float* bdense = (const float*)d_in[5];  // (1,)
    const float* Wmlp   = (const float*)d_in[6];  // (E+C, C)
    const float* bmlp   = (const float*)d_in[7];  // (C,)

    float* out_ctx  = (float*)d_out;                       // (U,I,C)
    float* out_attn = (float*)d_out + (size_t)U * I * C;   // (U,I,J)

    cudaFuncSetAttribute(mega_kernel,
                         cudaFuncAttributeMaxDynamicSharedMemorySize, SMEM_TOTAL);

    mega_kernel<<<dim3(2, U), 512, SMEM_TOTAL>>>(target, inter, user, mask,
                                                 wdense, bdense, Wmlp, bmlp,
                                                 out_ctx, out_attn);
}